// round 1
// baseline (speedup 1.0000x reference)
#include <cuda_runtime.h>
#include <math.h>

// Problem constants
#define N_B   16
#define C_DIM 256
#define HW    4096
#define K_A   512
#define M_ROWS (N_B * HW)          // 65536
#define EPS   1e-12f
#define INV_T 3.33333333333333f    // 1/0.3

// ---------------- scratch (__device__ globals; no runtime allocs) ----------
__device__ float g_A[(size_t)M_ROWS * K_A];     // 128 MB: A0 = exp(scores/T), [m][j]
__device__ float g_sx[N_B * C_DIM * K_A];       // 8 MB: normalized anchors [n][c][j]
__device__ float g_invn[M_ROWS];                // 1/||x||_c per (n,p)
__device__ float g_u[M_ROWS];
__device__ float g_colsum[K_A];
__device__ float g_t[K_A];
__device__ float g_v[K_A];
__device__ float g_S0;

// ---------------- init: zero colsum -----------------------------------------
__global__ void k_init() {
    int t = threadIdx.x;
    if (t < K_A) { g_colsum[t] = 0.0f; g_t[t] = 0.0f; }
}

// ---------------- per-pixel inverse L2 norm over channels -------------------
__global__ void k_norm(const float* __restrict__ x) {
    int p = blockIdx.x * blockDim.x + threadIdx.x;   // 0..65535
    int n  = p >> 12;
    int pp = p & (HW - 1);
    const float* base = x + (size_t)n * C_DIM * HW + pp;
    float acc = 0.0f;
#pragma unroll 8
    for (int c = 0; c < C_DIM; c++) {
        float v = base[(size_t)c * HW];
        acc += v * v;
    }
    g_invn[p] = 1.0f / fmaxf(sqrtf(acc), EPS);
}

// ---------------- gather normalized anchors: sx[n][c][j] --------------------
__global__ void k_gather(const float* __restrict__ x, const int* __restrict__ idx) {
    int g = blockIdx.x * blockDim.x + threadIdx.x;   // 0 .. 16*256*512-1
    int j = g & (K_A - 1);
    int c = (g >> 9) & (C_DIM - 1);
    int n = g >> 17;
    int p = idx[j];
    float val = x[((size_t)(n * C_DIM + c)) * HW + p] * g_invn[(n << 12) + p];
    g_sx[g] = val;
}

// ---------------- GEMM1: scores -> exp -> A0, + column sums -----------------
// Per n: S[j,p] = sum_c sx[c][j] * (x[c][p]*invn[p]);  A0[(n*4096+p)][j]=exp(S/T)
// grid (32 p-tiles, 4 j-tiles, 16 n), block 256, tile 128x128x16, 8x8/thread
__global__ void k_gemm1(const float* __restrict__ x) {
    __shared__ float As[16][128];   // [c][j]
    __shared__ float Bs[16][128];   // [c][p]
    __shared__ float red[16][128];  // column-sum reduction

    int n  = blockIdx.z;
    int j0 = blockIdx.y * 128;
    int p0 = blockIdx.x * 128;
    int tid = threadIdx.x;
    int tx = tid & 15;    // -> j
    int ty = tid >> 4;    // -> p

    const float* xb  = x + (size_t)n * C_DIM * HW;
    const float* sxb = g_sx + (size_t)n * C_DIM * K_A;

    // hoist invn multipliers for this thread's two B-load slots
    int f4a = tid & 31, f4b = (tid + 256) & 31;
    float inv0[4], inv1[4];
#pragma unroll
    for (int i = 0; i < 4; i++) {
        inv0[i] = g_invn[(n << 12) + p0 + f4a * 4 + i];
        inv1[i] = g_invn[(n << 12) + p0 + f4b * 4 + i];
    }

    float acc[8][8];   // [p][j]
#pragma unroll
    for (int a = 0; a < 8; a++)
#pragma unroll
        for (int b = 0; b < 8; b++) acc[a][b] = 0.0f;

    for (int kt = 0; kt < C_DIM / 16; kt++) {
        int c0 = kt * 16;
#pragma unroll
        for (int r = 0; r < 2; r++) {
            int q  = tid + r * 256;
            int cc = q >> 5, f4 = q & 31;
            float4 a4 = *(const float4*)(sxb + (size_t)(c0 + cc) * K_A + j0 + f4 * 4);
            *(float4*)(&As[cc][f4 * 4]) = a4;
            float4 b4 = *(const float4*)(xb + (size_t)(c0 + cc) * HW + p0 + f4 * 4);
            const float* iv = r ? inv1 : inv0;
            b4.x *= iv[0]; b4.y *= iv[1]; b4.z *= iv[2]; b4.w *= iv[3];
            *(float4*)(&Bs[cc][f4 * 4]) = b4;
        }
        __syncthreads();
#pragma unroll
        for (int kk = 0; kk < 16; kk++) {
            float a[8], b[8];
#pragma unroll
            for (int i = 0; i < 8; i++) a[i] = As[kk][tx * 8 + i];
#pragma unroll
            for (int i = 0; i < 8; i++) b[i] = Bs[kk][ty * 8 + i];
#pragma unroll
            for (int ii = 0; ii < 8; ii++)
#pragma unroll
                for (int i = 0; i < 8; i++) acc[ii][i] += a[i] * b[ii];
        }
        __syncthreads();
    }

    // epilogue: exp, store A0, accumulate column sums
    float colpart[8];
#pragma unroll
    for (int i = 0; i < 8; i++) colpart[i] = 0.0f;
#pragma unroll
    for (int ii = 0; ii < 8; ii++) {
        int p = p0 + ty * 8 + ii;
        size_t rowoff = ((size_t)(n << 12) + p) * K_A + j0 + tx * 8;
        float e[8];
#pragma unroll
        for (int i = 0; i < 8; i++) {
            e[i] = __expf(acc[ii][i] * INV_T);
            colpart[i] += e[i];
        }
        *(float4*)(g_A + rowoff)     = make_float4(e[0], e[1], e[2], e[3]);
        *(float4*)(g_A + rowoff + 4) = make_float4(e[4], e[5], e[6], e[7]);
    }
#pragma unroll
    for (int i = 0; i < 8; i++) red[ty][tx * 8 + i] = colpart[i];
    __syncthreads();
    if (tid < 128) {
        float s = 0.0f;
#pragma unroll
        for (int t = 0; t < 16; t++) s += red[t][tid];
        atomicAdd(&g_colsum[j0 + tid], s);
    }
}

// ---------------- v1 from column sums + total mass --------------------------
__global__ void k_v1() {
    __shared__ float sr[K_A];
    int tid = threadIdx.x;
    float c = g_colsum[tid];
    sr[tid] = c;
    __syncthreads();
    for (int s = K_A / 2; s > 0; s >>= 1) {
        if (tid < s) sr[tid] += sr[tid + s];
        __syncthreads();
    }
    float S0 = sr[0];
    if (tid == 0) g_S0 = S0;
    // iter-1 col normalize (u0 = 1/S0, v0 = 1):  v = 1/max(colsum/S0, eps)
    g_v[tid] = 1.0f / fmaxf(c / S0, EPS);
    g_t[tid] = 0.0f;
}

// ---------------- fused row pass + next col pass ----------------------------
// given v: d_m = A0[m,:].v ; u_m = u_old/max(u_old*d, eps); t_j += A0[m,j]*u_m
__global__ void k_fpass(int first, int compute_t) {
    __shared__ float vs[K_A];
    __shared__ float ts[K_A];
    int tid = threadIdx.x;
    vs[tid] = g_v[tid]; vs[tid + 256] = g_v[tid + 256];
    ts[tid] = 0.0f;     ts[tid + 256] = 0.0f;
    __syncthreads();

    int warp = tid >> 5, lane = tid & 31;
    int stride = gridDim.x * 8;
    int gw = blockIdx.x * 8 + warp;
    float S0inv = 1.0f / g_S0;

    float tp[16];
#pragma unroll
    for (int i = 0; i < 16; i++) tp[i] = 0.0f;

    for (int m = gw; m < M_ROWS; m += stride) {
        const float* row = g_A + (size_t)m * K_A + lane * 16;
        float4 r0 = *(const float4*)(row);
        float4 r1 = *(const float4*)(row + 4);
        float4 r2 = *(const float4*)(row + 8);
        float4 r3 = *(const float4*)(row + 12);
        const float* vv = vs + lane * 16;
        float d = r0.x * vv[0] + r0.y * vv[1] + r0.z * vv[2] + r0.w * vv[3]
                + r1.x * vv[4] + r1.y * vv[5] + r1.z * vv[6] + r1.w * vv[7]
                + r2.x * vv[8] + r2.y * vv[9] + r2.z * vv[10] + r2.w * vv[11]
                + r3.x * vv[12] + r3.y * vv[13] + r3.z * vv[14] + r3.w * vv[15];
#pragma unroll
        for (int off = 16; off > 0; off >>= 1) d += __shfl_xor_sync(0xFFFFFFFFu, d, off);
        float u_old = first ? S0inv : g_u[m];
        float u_new = u_old / fmaxf(u_old * d, EPS);
        if (lane == 0) g_u[m] = u_new;
        if (compute_t) {
            tp[0]  += r0.x * u_new; tp[1]  += r0.y * u_new; tp[2]  += r0.z * u_new; tp[3]  += r0.w * u_new;
            tp[4]  += r1.x * u_new; tp[5]  += r1.y * u_new; tp[6]  += r1.z * u_new; tp[7]  += r1.w * u_new;
            tp[8]  += r2.x * u_new; tp[9]  += r2.y * u_new; tp[10] += r2.z * u_new; tp[11] += r2.w * u_new;
            tp[12] += r3.x * u_new; tp[13] += r3.y * u_new; tp[14] += r3.z * u_new; tp[15] += r3.w * u_new;
        }
    }
    if (compute_t) {
#pragma unroll
        for (int i = 0; i < 16; i++) atomicAdd(&ts[lane * 16 + i], tp[i]);
        __syncthreads();
        atomicAdd(&g_t[tid], ts[tid]);
        atomicAdd(&g_t[tid + 256], ts[tid + 256]);
    }
}

// ---------------- v update between fused passes -----------------------------
__global__ void k_vupd() {
    int tid = threadIdx.x;
    float v = g_v[tid], t = g_t[tid];
    g_v[tid] = v / fmaxf(v * t, EPS);
    g_t[tid] = 0.0f;
}

// ---------------- GEMM2: out[n,c,p] = u_m * sum_j sx[c][j]*A0[m][j]*v[j] ----
// grid (32 p-tiles, 2 c-tiles, 16 n), block 256, tile 128x128x16, 8x8/thread
__global__ void k_gemm2(float* __restrict__ out) {
    __shared__ float As[16][132];   // [j][c]
    __shared__ float Bs[16][132];   // [j][p]
    __shared__ float vsh[K_A];

    int n  = blockIdx.z;
    int c0 = blockIdx.y * 128;
    int p0 = blockIdx.x * 128;
    int tid = threadIdx.x;
    int tx = tid & 15;    // -> p
    int ty = tid >> 4;    // -> c

    vsh[tid] = g_v[tid]; vsh[tid + 256] = g_v[tid + 256];

    const float* sxb = g_sx + (size_t)n * C_DIM * K_A;

    float acc[8][8];   // [c][p]
#pragma unroll
    for (int a = 0; a < 8; a++)
#pragma unroll
        for (int b = 0; b < 8; b++) acc[a][b] = 0.0f;

    __syncthreads();

    for (int kt = 0; kt < K_A / 16; kt++) {
        int j0 = kt * 16;
#pragma unroll
        for (int r = 0; r < 2; r++) {
            int q  = tid + r * 256;
            int rr = q >> 2, f4 = q & 3;
            // A tile: sx[c0+rr][j0 + f4*4 .. +3] -> As[jloc][c]
            float4 a4 = *(const float4*)(sxb + (size_t)(c0 + rr) * K_A + j0 + f4 * 4);
            As[f4 * 4 + 0][rr] = a4.x;
            As[f4 * 4 + 1][rr] = a4.y;
            As[f4 * 4 + 2][rr] = a4.z;
            As[f4 * 4 + 3][rr] = a4.w;
            // B tile: A0[(n*4096+p0+rr)][j0 + f4*4 .. +3] * v -> Bs[jloc][p]
            float4 b4 = *(const float4*)(g_A + ((size_t)(n << 12) + p0 + rr) * K_A + j0 + f4 * 4);
            Bs[f4 * 4 + 0][rr] = b4.x * vsh[j0 + f4 * 4 + 0];
            Bs[f4 * 4 + 1][rr] = b4.y * vsh[j0 + f4 * 4 + 1];
            Bs[f4 * 4 + 2][rr] = b4.z * vsh[j0 + f4 * 4 + 2];
            Bs[f4 * 4 + 3][rr] = b4.w * vsh[j0 + f4 * 4 + 3];
        }
        __syncthreads();
#pragma unroll
        for (int kk = 0; kk < 16; kk++) {
            float a[8], b[8];
#pragma unroll
            for (int i = 0; i < 8; i++) a[i] = As[kk][ty * 8 + i];
#pragma unroll
            for (int i = 0; i < 8; i++) b[i] = Bs[kk][tx * 8 + i];
#pragma unroll
            for (int ci = 0; ci < 8; ci++)
#pragma unroll
                for (int pi = 0; pi < 8; pi++) acc[ci][pi] += a[ci] * b[pi];
        }
        __syncthreads();
    }

    // scale by u (final row normalization) and write
    float ureg[8];
#pragma unroll
    for (int pi = 0; pi < 8; pi++) ureg[pi] = g_u[(n << 12) + p0 + tx * 8 + pi];
#pragma unroll
    for (int ci = 0; ci < 8; ci++) {
        int c = c0 + ty * 8 + ci;
        size_t o = ((size_t)(n * C_DIM + c)) * HW + p0 + tx * 8;
        *(float4*)(out + o) = make_float4(acc[ci][0] * ureg[0], acc[ci][1] * ureg[1],
                                          acc[ci][2] * ureg[2], acc[ci][3] * ureg[3]);
        *(float4*)(out + o + 4) = make_float4(acc[ci][4] * ureg[4], acc[ci][5] * ureg[5],
                                              acc[ci][6] * ureg[6], acc[ci][7] * ureg[7]);
    }
}

// ---------------- launcher ---------------------------------------------------
extern "C" void kernel_launch(void* const* d_in, const int* in_sizes, int n_in,
                              void* d_out, int out_size) {
    const float* x  = (const float*)d_in[0];
    const int* idx  = (const int*)d_in[1];
    float* out      = (float*)d_out;

    k_init<<<1, 512>>>();
    k_norm<<<M_ROWS / 256, 256>>>(x);
    k_gather<<<(N_B * C_DIM * K_A) / 256, 256>>>(x, idx);
    k_gemm1<<<dim3(32, 4, 16), 256>>>(x);
    k_v1<<<1, 512>>>();
    k_fpass<<<296, 256>>>(1, 1);   // iter1 row + iter2 colsums
    k_vupd<<<1, 512>>>();
    k_fpass<<<296, 256>>>(0, 1);   // iter2 row + iter3 colsums
    k_vupd<<<1, 512>>>();
    k_fpass<<<296, 256>>>(0, 1);   // iter3 row + iter4 colsums
    k_vupd<<<1, 512>>>();
    k_fpass<<<296, 256>>>(0, 0);   // iter4 row (final u)
    k_gemm2<<<dim3(32, 2, 16), 256>>>(out);
}

// round 6
// speedup vs baseline: 1.8007x; 1.8007x over previous
#include <cuda_runtime.h>
#include <math.h>

// Problem constants
#define N_B   16
#define C_DIM 256
#define HW    4096
#define K_A   512
#define M_ROWS (N_B * HW)          // 65536
#define EPS   1e-12f
#define INV_T 3.33333333333333f    // 1/0.3

// ---------------- scratch (__device__ globals; no runtime allocs) ----------
__device__ float g_A[(size_t)M_ROWS * K_A];     // 128 MB: A0 = exp(scores/T), [m][j]
__device__ float g_sx[N_B * C_DIM * K_A];       // 8 MB: normalized anchors [n][c][j]
__device__ float g_invn[M_ROWS];                // 1/||x||_c per (n,p)
__device__ float g_u[M_ROWS];
__device__ float g_colsum[K_A];
__device__ float g_t[K_A];
__device__ float g_v[K_A];
__device__ float g_S0;

__device__ __forceinline__ unsigned cvt_tf32(float f) {
    unsigned r; asm("cvt.rna.tf32.f32 %0, %1;" : "=r"(r) : "f"(f)); return r;
}
__device__ __forceinline__ float tf32f(float f) { return __uint_as_float(cvt_tf32(f)); }

#define MMA_TF32(d, a, b) asm volatile( \
    "mma.sync.aligned.m16n8k8.row.col.f32.tf32.tf32.f32 " \
    "{%0,%1,%2,%3},{%4,%5,%6,%7},{%8,%9},{%0,%1,%2,%3};" \
    : "+f"(d[0]), "+f"(d[1]), "+f"(d[2]), "+f"(d[3]) \
    : "r"(a[0]), "r"(a[1]), "r"(a[2]), "r"(a[3]), "r"(b[0]), "r"(b[1]))

// ---------------- init -------------------------------------------------------
__global__ void k_init() {
    int t = threadIdx.x;
    if (t < K_A) { g_colsum[t] = 0.0f; g_t[t] = 0.0f; }
}

// ---------------- per-pixel inverse L2 norm over channels -------------------
__global__ void k_norm(const float* __restrict__ x) {
    int p = blockIdx.x * blockDim.x + threadIdx.x;   // 0..65535
    int n  = p >> 12;
    int pp = p & (HW - 1);
    const float* base = x + (size_t)n * C_DIM * HW + pp;
    float acc = 0.0f;
#pragma unroll 8
    for (int c = 0; c < C_DIM; c++) {
        float v = base[(size_t)c * HW];
        acc += v * v;
    }
    g_invn[p] = 1.0f / fmaxf(sqrtf(acc), EPS);
}

// ---------------- gather normalized anchors: sx[n][c][j] --------------------
__global__ void k_gather(const float* __restrict__ x, const int* __restrict__ idx) {
    int g = blockIdx.x * blockDim.x + threadIdx.x;   // 0 .. 16*256*512-1
    int j = g & (K_A - 1);
    int c = (g >> 9) & (C_DIM - 1);
    int n = g >> 17;
    int p = idx[j];
    float val = x[((size_t)(n * C_DIM + c)) * HW + p] * g_invn[(n << 12) + p];
    g_sx[g] = val;
}

// ---------------- GEMM1 (TF32 MMA): scores -> exp -> A0, + column sums ------
// Per n: S[p,j] = sum_c (x[c][p]*invn[p]) * sx[c][j];  A0[m][j] = exp(S/T)
// grid (32 p-tiles, 4 j-tiles, 16 n), block 256 = 8 warps (2 M x 4 N)
// block tile M(p)=128, N(j)=128, K(c)=16/chunk; warp tile 64x32; m16n8k8 tf32
__global__ __launch_bounds__(256) void k_gemm1(const float* __restrict__ x) {
    __shared__ float Xs[16][136];   // [c][p] tf32-rounded (A operand, row=p col=c)
    __shared__ float Ss[16][136];   // [c][j] tf32-rounded (B operand, k=c n=j)
    __shared__ float redsh[128];

    int n  = blockIdx.z;
    int j0 = blockIdx.y * 128;
    int p0 = blockIdx.x * 128;
    int tid = threadIdx.x;
    int lane = tid & 31, warp = tid >> 5;
    int warpM = warp >> 2, warpN = warp & 3;
    int gid = lane >> 2, tig = lane & 3;

    if (tid < 128) redsh[tid] = 0.0f;

    const float* xb  = x + (size_t)n * C_DIM * HW;
    const float* sxb = g_sx + (size_t)n * C_DIM * K_A;

    int f4  = tid & 31;
    int ccb = tid >> 5;
    float inv[4];
#pragma unroll
    for (int i = 0; i < 4; i++) inv[i] = g_invn[(n << 12) + p0 + f4 * 4 + i];

    float acc[4][4][4];
#pragma unroll
    for (int a = 0; a < 4; a++)
#pragma unroll
        for (int b = 0; b < 4; b++)
#pragma unroll
            for (int c = 0; c < 4; c++) acc[a][b][c] = 0.0f;

    for (int kt = 0; kt < C_DIM / 16; kt++) {
        int cb = kt * 16;
#pragma unroll
        for (int r = 0; r < 2; r++) {
            int cc = ccb + r * 8;
            float4 s4 = *(const float4*)(sxb + (size_t)(cb + cc) * K_A + j0 + f4 * 4);
            *(float4*)(&Ss[cc][f4 * 4]) =
                make_float4(tf32f(s4.x), tf32f(s4.y), tf32f(s4.z), tf32f(s4.w));
            float4 b4 = *(const float4*)(xb + (size_t)(cb + cc) * HW + p0 + f4 * 4);
            *(float4*)(&Xs[cc][f4 * 4]) =
                make_float4(tf32f(b4.x * inv[0]), tf32f(b4.y * inv[1]),
                            tf32f(b4.z * inv[2]), tf32f(b4.w * inv[3]));
        }
        __syncthreads();
#pragma unroll
        for (int ks = 0; ks < 2; ks++) {
            int ca = ks * 8 + tig;
            unsigned a[4][4], b[4][2];
#pragma unroll
            for (int mt = 0; mt < 4; mt++) {
                int pr = warpM * 64 + mt * 16 + gid;
                a[mt][0] = __float_as_uint(Xs[ca][pr]);
                a[mt][1] = __float_as_uint(Xs[ca][pr + 8]);
                a[mt][2] = __float_as_uint(Xs[ca + 4][pr]);
                a[mt][3] = __float_as_uint(Xs[ca + 4][pr + 8]);
            }
#pragma unroll
            for (int nt = 0; nt < 4; nt++) {
                int jc = warpN * 32 + nt * 8 + gid;
                b[nt][0] = __float_as_uint(Ss[ca][jc]);
                b[nt][1] = __float_as_uint(Ss[ca + 4][jc]);
            }
#pragma unroll
            for (int mt = 0; mt < 4; mt++)
#pragma unroll
                for (int nt = 0; nt < 4; nt++) MMA_TF32(acc[mt][nt], a[mt], b[nt]);
        }
        __syncthreads();
    }

    // epilogue: exp, store A0 (float2), accumulate column sums
    float s[4][2];
#pragma unroll
    for (int nt = 0; nt < 4; nt++) { s[nt][0] = 0.0f; s[nt][1] = 0.0f; }
#pragma unroll
    for (int mt = 0; mt < 4; mt++) {
        int p = p0 + warpM * 64 + mt * 16 + gid;
        size_t base = ((size_t)(n << 12) + p) * K_A + j0 + warpN * 32;
#pragma unroll
        for (int nt = 0; nt < 4; nt++) {
            float e0 = __expf(acc[mt][nt][0] * INV_T);
            float e1 = __expf(acc[mt][nt][1] * INV_T);
            float e2 = __expf(acc[mt][nt][2] * INV_T);
            float e3 = __expf(acc[mt][nt][3] * INV_T);
            *(float2*)(g_A + base + nt * 8 + tig * 2)             = make_float2(e0, e1);
            *(float2*)(g_A + base + (size_t)8 * K_A + nt * 8 + tig * 2) = make_float2(e2, e3);
            s[nt][0] += e0 + e2;
            s[nt][1] += e1 + e3;
        }
    }
#pragma unroll
    for (int nt = 0; nt < 4; nt++) {
        float v0 = s[nt][0], v1 = s[nt][1];
#pragma unroll
        for (int off = 4; off < 32; off <<= 1) {
            v0 += __shfl_xor_sync(0xFFFFFFFFu, v0, off);
            v1 += __shfl_xor_sync(0xFFFFFFFFu, v1, off);
        }
        if (lane < 4) {
            atomicAdd(&redsh[warpN * 32 + nt * 8 + lane * 2],     v0);
            atomicAdd(&redsh[warpN * 32 + nt * 8 + lane * 2 + 1], v1);
        }
    }
    __syncthreads();
    if (tid < 128) atomicAdd(&g_colsum[j0 + tid], redsh[tid]);
}

// ---------------- v1 from column sums + total mass --------------------------
__global__ void k_v1() {
    __shared__ float sr[K_A];
    int tid = threadIdx.x;
    float c = g_colsum[tid];
    sr[tid] = c;
    __syncthreads();
    for (int s = K_A / 2; s > 0; s >>= 1) {
        if (tid < s) sr[tid] += sr[tid + s];
        __syncthreads();
    }
    float S0 = sr[0];
    if (tid == 0) g_S0 = S0;
    g_v[tid] = 1.0f / fmaxf(c / S0, EPS);
    g_t[tid] = 0.0f;
}

// ---------------- fused row pass + next col pass ----------------------------
__global__ void k_fpass(int first, int compute_t) {
    __shared__ float vs[K_A];
    __shared__ float ts[K_A];
    int tid = threadIdx.x;
    vs[tid] = g_v[tid]; vs[tid + 256] = g_v[tid + 256];
    ts[tid] = 0.0f;     ts[tid + 256] = 0.0f;
    __syncthreads();

    int warp = tid >> 5, lane = tid & 31;
    int stride = gridDim.x * 8;
    int gw = blockIdx.x * 8 + warp;
    float S0inv = 1.0f / g_S0;

    float tp[16];
#pragma unroll
    for (int i = 0; i < 16; i++) tp[i] = 0.0f;

    for (int m = gw; m < M_ROWS; m += stride) {
        const float* row = g_A + (size_t)m * K_A + lane * 16;
        float4 r0 = *(const float4*)(row);
        float4 r1 = *(const float4*)(row + 4);
        float4 r2 = *(const float4*)(row + 8);
        float4 r3 = *(const float4*)(row + 12);
        const float* vv = vs + lane * 16;
        float d = r0.x * vv[0] + r0.y * vv[1] + r0.z * vv[2] + r0.w * vv[3]
                + r1.x * vv[4] + r1.y * vv[5] + r1.z * vv[6] + r1.w * vv[7]
                + r2.x * vv[8] + r2.y * vv[9] + r2.z * vv[10] + r2.w * vv[11]
                + r3.x * vv[12] + r3.y * vv[13] + r3.z * vv[14] + r3.w * vv[15];
#pragma unroll
        for (int off = 16; off > 0; off >>= 1) d += __shfl_xor_sync(0xFFFFFFFFu, d, off);
        float u_old = first ? S0inv : g_u[m];
        float u_new = u_old / fmaxf(u_old * d, EPS);
        if (lane == 0) g_u[m] = u_new;
        if (compute_t) {
            tp[0]  += r0.x * u_new; tp[1]  += r0.y * u_new; tp[2]  += r0.z * u_new; tp[3]  += r0.w * u_new;
            tp[4]  += r1.x * u_new; tp[5]  += r1.y * u_new; tp[6]  += r1.z * u_new; tp[7]  += r1.w * u_new;
            tp[8]  += r2.x * u_new; tp[9]  += r2.y * u_new; tp[10] += r2.z * u_new; tp[11] += r2.w * u_new;
            tp[12] += r3.x * u_new; tp[13] += r3.y * u_new; tp[14] += r3.z * u_new; tp[15] += r3.w * u_new;
        }
    }
    if (compute_t) {
#pragma unroll
        for (int i = 0; i < 16; i++) atomicAdd(&ts[lane * 16 + i], tp[i]);
        __syncthreads();
        atomicAdd(&g_t[tid], ts[tid]);
        atomicAdd(&g_t[tid + 256], ts[tid + 256]);
    }
}

// ---------------- v update between fused passes -----------------------------
__global__ void k_vupd() {
    int tid = threadIdx.x;
    float v = g_v[tid], t = g_t[tid];
    g_v[tid] = v / fmaxf(v * t, EPS);
    g_t[tid] = 0.0f;
}

// ---------------- GEMM2 (TF32 MMA) + fused 4th row pass ---------------------
// out[n,c,p] = u_p * sum_j sx[c][j] * A0[m][j] * v[j];  u_p computed in-kernel
// from d_p = sum_j A0[m][j]*v[j] accumulated while loading tiles.
// grid (32 p-tiles, 2 c-tiles, 16 n), block 256; M(c)=128, N(p)=128, K(j)=16/chunk
__global__ __launch_bounds__(256) void k_gemm2(float* __restrict__ out) {
    __shared__ float As[16][132];   // [j][c] tf32 (A operand, row=c col=j)
    __shared__ float Bs[16][132];   // [j][p] tf32 (B operand = A0*v, k=j n=p)
    __shared__ float vsh[K_A];
    __shared__ float dred[128];
    __shared__ float ush[128];

    int n  = blockIdx.z;
    int c0 = blockIdx.y * 128;
    int p0 = blockIdx.x * 128;
    int tid = threadIdx.x;
    int lane = tid & 31, warp = tid >> 5;
    int warpM = warp >> 2, warpN = warp & 3;
    int gid = lane >> 2, tig = lane & 3;

    vsh[tid] = g_v[tid]; vsh[tid + 256] = g_v[tid + 256];
    if (tid < 128) dred[tid] = 0.0f;

    const float* sxb = g_sx + (size_t)n * C_DIM * K_A;

    float acc[4][4][4];
#pragma unroll
    for (int a = 0; a < 4; a++)
#pragma unroll
        for (int b = 0; b < 4; b++)
#pragma unroll
            for (int c = 0; c < 4; c++) acc[a][b][c] = 0.0f;

    int rr0 = tid >> 2, f40 = tid & 3;   // r=0 slot
    int rr1 = rr0 + 64;                  // r=1 slot (f4 identical)
    float dp0 = 0.0f, dp1 = 0.0f;

    __syncthreads();

    for (int kt = 0; kt < K_A / 16; kt++) {
        int j0 = kt * 16;
        {   // r = 0
            float4 a4 = *(const float4*)(sxb + (size_t)(c0 + rr0) * K_A + j0 + f40 * 4);
            As[f40 * 4 + 0][rr0] = tf32f(a4.x);
            As[f40 * 4 + 1][rr0] = tf32f(a4.y);
            As[f40 * 4 + 2][rr0] = tf32f(a4.z);
            As[f40 * 4 + 3][rr0] = tf32f(a4.w);
            float4 b4 = *(const float4*)(g_A + ((size_t)(n << 12) + p0 + rr0) * K_A + j0 + f40 * 4);
            float m0 = b4.x * vsh[j0 + f40 * 4 + 0];
            float m1 = b4.y * vsh[j0 + f40 * 4 + 1];
            float m2 = b4.z * vsh[j0 + f40 * 4 + 2];
            float m3 = b4.w * vsh[j0 + f40 * 4 + 3];
            dp0 += m0 + m1 + m2 + m3;
            Bs[f40 * 4 + 0][rr0] = tf32f(m0);
            Bs[f40 * 4 + 1][rr0] = tf32f(m1);
            Bs[f40 * 4 + 2][rr0] = tf32f(m2);
            Bs[f40 * 4 + 3][rr0] = tf32f(m3);
        }
        {   // r = 1
            float4 a4 = *(const float4*)(sxb + (size_t)(c0 + rr1) * K_A + j0 + f40 * 4);
            As[f40 * 4 + 0][rr1] = tf32f(a4.x);
            As[f40 * 4 + 1][rr1] = tf32f(a4.y);
            As[f40 * 4 + 2][rr1] = tf32f(a4.z);
            As[f40 * 4 + 3][rr1] = tf32f(a4.w);
            float4 b4 = *(const float4*)(g_A + ((size_t)(n << 12) + p0 + rr1) * K_A + j0 + f40 * 4);
            float m0 = b4.x * vsh[j0 + f40 * 4 + 0];
            float m1 = b4.y * vsh[j0 + f40 * 4 + 1];
            float m2 = b4.z * vsh[j0 + f40 * 4 + 2];
            float m3 = b4.w * vsh[j0 + f40 * 4 + 3];
            dp1 += m0 + m1 + m2 + m3;
            Bs[f40 * 4 + 0][rr1] = tf32f(m0);
            Bs[f40 * 4 + 1][rr1] = tf32f(m1);
            Bs[f40 * 4 + 2][rr1] = tf32f(m2);
            Bs[f40 * 4 + 3][rr1] = tf32f(m3);
        }
        __syncthreads();
#pragma unroll
        for (int ks = 0; ks < 2; ks++) {
            int ca = ks * 8 + tig;
            unsigned a[4][4], b[4][2];
#pragma unroll
            for (int mt = 0; mt < 4; mt++) {
                int cr = warpM * 64 + mt * 16 + gid;
                a[mt][0] = __float_as_uint(As[ca][cr]);
                a[mt][1] = __float_as_uint(As[ca][cr + 8]);
                a[mt][2] = __float_as_uint(As[ca + 4][cr]);
                a[mt][3] = __float_as_uint(As[ca + 4][cr + 8]);
            }
#pragma unroll
            for (int nt = 0; nt < 4; nt++) {
                int pc = warpN * 32 + nt * 8 + gid;
                b[nt][0] = __float_as_uint(Bs[ca][pc]);
                b[nt][1] = __float_as_uint(Bs[ca + 4][pc]);
            }
#pragma unroll
            for (int mt = 0; mt < 4; mt++)
#pragma unroll
                for (int nt = 0; nt < 4; nt++) MMA_TF32(acc[mt][nt], a[mt], b[nt]);
        }
        __syncthreads();
    }

    // finalize d -> u (4th Sinkhorn row pass, fused)
    atomicAdd(&dred[rr0], dp0);
    atomicAdd(&dred[rr1], dp1);
    __syncthreads();
    if (tid < 128) {
        float d  = dred[tid];
        float u3 = g_u[(n << 12) + p0 + tid];
        ush[tid] = u3 / fmaxf(u3 * d, EPS);
    }
    __syncthreads();

#pragma unroll
    for (int mt = 0; mt < 4; mt++) {
        int c = c0 + warpM * 64 + mt * 16 + gid;
#pragma unroll
        for (int nt = 0; nt < 4; nt++) {
            int pl = warpN * 32 + nt * 8 + tig * 2;
            float u0 = ush[pl], u1 = ush[pl + 1];
            size_t o = ((size_t)(n * C_DIM + c)) * HW + p0 + pl;
            *(float2*)(out + o) = make_float2(acc[mt][nt][0] * u0, acc[mt][nt][1] * u1);
            *(float2*)(out + o + (size_t)8 * HW) =
                make_float2(acc[mt][nt][2] * u0, acc[mt][nt][3] * u1);
        }
    }
}

// ---------------- launcher ---------------------------------------------------
extern "C" void kernel_launch(void* const* d_in, const int* in_sizes, int n_in,
                              void* d_out, int out_size) {
    const float* x  = (const float*)d_in[0];
    const int* idx  = (const int*)d_in[1];
    float* out      = (float*)d_out;

    k_init<<<1, 512>>>();
    k_norm<<<M_ROWS / 256, 256>>>(x);
    k_gather<<<(N_B * C_DIM * K_A) / 256, 256>>>(x, idx);
    k_gemm1<<<dim3(32, 4, 16), 256>>>(x);
    k_v1<<<1, 512>>>();
    k_fpass<<<296, 256>>>(1, 1);   // iter1 row + iter2 colsums
    k_vupd<<<1, 512>>>();
    k_fpass<<<296, 256>>>(0, 1);   // iter2 row + iter3 colsums
    k_vupd<<<1, 512>>>();
    k_fpass<<<296, 256>>>(0, 1);   // iter3 row + iter4 colsums
    k_vupd<<<1, 512>>>();
    k_gemm2<<<dim3(32, 2, 16), 256>>>(out);  // iter4 row fused + reconstruction
}

// round 15
// speedup vs baseline: 2.3120x; 1.2839x over previous
#include <cuda_runtime.h>
#include <cuda_fp16.h>
#include <math.h>

// Problem constants
#define N_B   16
#define C_DIM 256
#define HW    4096
#define K_A   512
#define M_ROWS (N_B * HW)          // 65536
#define EPS   1e-12f
#define INV_T 3.33333333333333f    // 1/0.3

// ---------------- scratch (__device__ globals; no runtime allocs) ----------
__device__ __align__(16) __half g_Ah[(size_t)M_ROWS * K_A]; // 64 MB: A0 = exp(scores/T)
__device__ float g_sx[N_B * C_DIM * K_A];       // 8 MB: normalized anchors [n][c][j]
__device__ float g_invn[M_ROWS];                // 1/||x||_c per (n,p)
__device__ float g_u[M_ROWS];
__device__ float g_colsum[K_A];
__device__ float g_t[K_A];
__device__ float g_v[K_A];
__device__ float g_vs[K_A];                     // v / vmax (for fp16 gemm2)
__device__ float g_vmax;
__device__ float g_S0;

__device__ __forceinline__ unsigned cvt_tf32(float f) {
    unsigned r; asm("cvt.rna.tf32.f32 %0, %1;" : "=r"(r) : "f"(f)); return r;
}
__device__ __forceinline__ float tf32f(float f) { return __uint_as_float(cvt_tf32(f)); }

#define MMA_TF32(d, a, b) asm volatile( \
    "mma.sync.aligned.m16n8k8.row.col.f32.tf32.tf32.f32 " \
    "{%0,%1,%2,%3},{%4,%5,%6,%7},{%8,%9},{%0,%1,%2,%3};" \
    : "+f"(d[0]), "+f"(d[1]), "+f"(d[2]), "+f"(d[3]) \
    : "r"(a[0]), "r"(a[1]), "r"(a[2]), "r"(a[3]), "r"(b[0]), "r"(b[1]))

#define MMA_F16(d, a, b) asm volatile( \
    "mma.sync.aligned.m16n8k16.row.col.f32.f16.f16.f32 " \
    "{%0,%1,%2,%3},{%4,%5,%6,%7},{%8,%9},{%0,%1,%2,%3};" \
    : "+f"(d[0]), "+f"(d[1]), "+f"(d[2]), "+f"(d[3]) \
    : "r"(a[0]), "r"(a[1]), "r"(a[2]), "r"(a[3]), "r"(b[0]), "r"(b[1]))

// ---------------- init -------------------------------------------------------
__global__ void k_init() {
    int t = threadIdx.x;
    if (t < K_A) { g_colsum[t] = 0.0f; g_t[t] = 0.0f; }
}

// ---------------- per-pixel inverse L2 norm over channels -------------------
__global__ void k_norm(const float* __restrict__ x) {
    int p = blockIdx.x * blockDim.x + threadIdx.x;   // 0..65535
    int n  = p >> 12;
    int pp = p & (HW - 1);
    const float* base = x + (size_t)n * C_DIM * HW + pp;
    float acc = 0.0f;
#pragma unroll 8
    for (int c = 0; c < C_DIM; c++) {
        float v = base[(size_t)c * HW];
        acc += v * v;
    }
    g_invn[p] = 1.0f / fmaxf(sqrtf(acc), EPS);
}

// ---------------- gather normalized anchors: sx[n][c][j] --------------------
__global__ void k_gather(const float* __restrict__ x, const int* __restrict__ idx) {
    int g = blockIdx.x * blockDim.x + threadIdx.x;   // 0 .. 16*256*512-1
    int j = g & (K_A - 1);
    int c = (g >> 9) & (C_DIM - 1);
    int n = g >> 17;
    int p = idx[j];
    float val = x[((size_t)(n * C_DIM + c)) * HW + p] * g_invn[(n << 12) + p];
    g_sx[g] = val;
}

// ---------------- GEMM1 (TF32 MMA): scores -> exp -> A0(half) + column sums --
__global__ __launch_bounds__(256) void k_gemm1(const float* __restrict__ x) {
    __shared__ float Xs[16][136];   // [c][p] tf32-rounded
    __shared__ float Ss[16][136];   // [c][j] tf32-rounded
    __shared__ float redsh[128];

    int n  = blockIdx.z;
    int j0 = blockIdx.y * 128;
    int p0 = blockIdx.x * 128;
    int tid = threadIdx.x;
    int lane = tid & 31, warp = tid >> 5;
    int warpM = warp >> 2, warpN = warp & 3;
    int gid = lane >> 2, tig = lane & 3;

    if (tid < 128) redsh[tid] = 0.0f;

    const float* xb  = x + (size_t)n * C_DIM * HW;
    const float* sxb = g_sx + (size_t)n * C_DIM * K_A;

    int f4  = tid & 31;
    int ccb = tid >> 5;
    float inv[4];
#pragma unroll
    for (int i = 0; i < 4; i++) inv[i] = g_invn[(n << 12) + p0 + f4 * 4 + i];

    float acc[4][4][4];
#pragma unroll
    for (int a = 0; a < 4; a++)
#pragma unroll
        for (int b = 0; b < 4; b++)
#pragma unroll
            for (int c = 0; c < 4; c++) acc[a][b][c] = 0.0f;

    for (int kt = 0; kt < C_DIM / 16; kt++) {
        int cb = kt * 16;
#pragma unroll
        for (int r = 0; r < 2; r++) {
            int cc = ccb + r * 8;
            float4 s4 = *(const float4*)(sxb + (size_t)(cb + cc) * K_A + j0 + f4 * 4);
            *(float4*)(&Ss[cc][f4 * 4]) =
                make_float4(tf32f(s4.x), tf32f(s4.y), tf32f(s4.z), tf32f(s4.w));
            float4 b4 = *(const float4*)(xb + (size_t)(cb + cc) * HW + p0 + f4 * 4);
            *(float4*)(&Xs[cc][f4 * 4]) =
                make_float4(tf32f(b4.x * inv[0]), tf32f(b4.y * inv[1]),
                            tf32f(b4.z * inv[2]), tf32f(b4.w * inv[3]));
        }
        __syncthreads();
#pragma unroll
        for (int ks = 0; ks < 2; ks++) {
            int ca = ks * 8 + tig;
            unsigned a[4][4], b[4][2];
#pragma unroll
            for (int mt = 0; mt < 4; mt++) {
                int pr = warpM * 64 + mt * 16 + gid;
                a[mt][0] = __float_as_uint(Xs[ca][pr]);
                a[mt][1] = __float_as_uint(Xs[ca][pr + 8]);
                a[mt][2] = __float_as_uint(Xs[ca + 4][pr]);
                a[mt][3] = __float_as_uint(Xs[ca + 4][pr + 8]);
            }
#pragma unroll
            for (int nt = 0; nt < 4; nt++) {
                int jc = warpN * 32 + nt * 8 + gid;
                b[nt][0] = __float_as_uint(Ss[ca][jc]);
                b[nt][1] = __float_as_uint(Ss[ca + 4][jc]);
            }
#pragma unroll
            for (int mt = 0; mt < 4; mt++)
#pragma unroll
                for (int nt = 0; nt < 4; nt++) MMA_TF32(acc[mt][nt], a[mt], b[nt]);
        }
        __syncthreads();
    }

    // epilogue: exp, round to half, store, accumulate column sums of ROUNDED vals
    float s[4][2];
#pragma unroll
    for (int nt = 0; nt < 4; nt++) { s[nt][0] = 0.0f; s[nt][1] = 0.0f; }
#pragma unroll
    for (int mt = 0; mt < 4; mt++) {
        int p = p0 + warpM * 64 + mt * 16 + gid;
        size_t base = ((size_t)(n << 12) + p) * K_A + j0 + warpN * 32;
#pragma unroll
        for (int nt = 0; nt < 4; nt++) {
            __half2 h01 = __floats2half2_rn(__expf(acc[mt][nt][0] * INV_T),
                                            __expf(acc[mt][nt][1] * INV_T));
            __half2 h23 = __floats2half2_rn(__expf(acc[mt][nt][2] * INV_T),
                                            __expf(acc[mt][nt][3] * INV_T));
            *(__half2*)(g_Ah + base + nt * 8 + tig * 2)                 = h01;
            *(__half2*)(g_Ah + base + (size_t)8 * K_A + nt * 8 + tig * 2) = h23;
            float2 r01 = __half22float2(h01);
            float2 r23 = __half22float2(h23);
            s[nt][0] += r01.x + r23.x;
            s[nt][1] += r01.y + r23.y;
        }
    }
#pragma unroll
    for (int nt = 0; nt < 4; nt++) {
        float v0 = s[nt][0], v1 = s[nt][1];
#pragma unroll
        for (int off = 4; off < 32; off <<= 1) {
            v0 += __shfl_xor_sync(0xFFFFFFFFu, v0, off);
            v1 += __shfl_xor_sync(0xFFFFFFFFu, v1, off);
        }
        if (lane < 4) {
            atomicAdd(&redsh[warpN * 32 + nt * 8 + lane * 2],     v0);
            atomicAdd(&redsh[warpN * 32 + nt * 8 + lane * 2 + 1], v1);
        }
    }
    __syncthreads();
    if (tid < 128) atomicAdd(&g_colsum[j0 + tid], redsh[tid]);
}

// ---------------- v1 from column sums + total mass --------------------------
__global__ void k_v1() {
    __shared__ float sr[K_A];
    int tid = threadIdx.x;
    float c = g_colsum[tid];
    sr[tid] = c;
    __syncthreads();
    for (int s = K_A / 2; s > 0; s >>= 1) {
        if (tid < s) sr[tid] += sr[tid + s];
        __syncthreads();
    }
    float S0 = sr[0];
    if (tid == 0) g_S0 = S0;
    g_v[tid] = 1.0f / fmaxf(c / S0, EPS);
    g_t[tid] = 0.0f;
}

// ---------------- fused row pass + next col pass (half A) --------------------
__global__ void k_fpass(int first, int compute_t) {
    __shared__ float vs[K_A];
    __shared__ float ts[K_A];
    int tid = threadIdx.x;
    vs[tid] = g_v[tid]; vs[tid + 256] = g_v[tid + 256];
    ts[tid] = 0.0f;     ts[tid + 256] = 0.0f;
    __syncthreads();

    int warp = tid >> 5, lane = tid & 31;
    int stride = gridDim.x * 8;
    int gw = blockIdx.x * 8 + warp;
    float S0inv = 1.0f / g_S0;

    float tp[16];
#pragma unroll
    for (int i = 0; i < 16; i++) tp[i] = 0.0f;

    for (int m = gw; m < M_ROWS; m += stride) {
        const __half* row = g_Ah + (size_t)m * K_A + lane * 16;
        uint4 q0 = *(const uint4*)(row);
        uint4 q1 = *(const uint4*)(row + 8);
        unsigned us[8] = {q0.x, q0.y, q0.z, q0.w, q1.x, q1.y, q1.z, q1.w};
        float f[16];
#pragma unroll
        for (int w = 0; w < 8; w++) {
            float2 fw = __half22float2(*(__half2*)&us[w]);
            f[2 * w] = fw.x; f[2 * w + 1] = fw.y;
        }
        const float* vv = vs + lane * 16;
        float d = 0.0f;
#pragma unroll
        for (int i = 0; i < 16; i++) d += f[i] * vv[i];
#pragma unroll
        for (int off = 16; off > 0; off >>= 1) d += __shfl_xor_sync(0xFFFFFFFFu, d, off);
        float u_old = first ? S0inv : g_u[m];
        float u_new = u_old / fmaxf(u_old * d, EPS);
        if (lane == 0) g_u[m] = u_new;
        if (compute_t) {
#pragma unroll
            for (int i = 0; i < 16; i++) tp[i] += f[i] * u_new;
        }
    }
    if (compute_t) {
#pragma unroll
        for (int i = 0; i < 16; i++) atomicAdd(&ts[lane * 16 + i], tp[i]);
        __syncthreads();
        atomicAdd(&g_t[tid], ts[tid]);
        atomicAdd(&g_t[tid + 256], ts[tid + 256]);
    }
}

// ---------------- v update; last call also produces scaled v -----------------
__global__ void k_vupd(int make_scaled) {
    __shared__ float sm[K_A];
    int tid = threadIdx.x;   // 512 threads
    float v = g_v[tid], t = g_t[tid];
    float vn = v / fmaxf(v * t, EPS);
    g_v[tid] = vn;
    g_t[tid] = 0.0f;
    if (make_scaled) {
        sm[tid] = vn;
        __syncthreads();
        for (int s = K_A / 2; s > 0; s >>= 1) {
            if (tid < s) sm[tid] = fmaxf(sm[tid], sm[tid + s]);
            __syncthreads();
        }
        float vmax = sm[0];
        if (tid == 0) g_vmax = vmax;
        g_vs[tid] = vn / vmax;
    }
}

// ---------------- GEMM2 (FP16 MMA) + fused 4th row pass ----------------------
// out[n,c,p] = u4_p * sum_j sx[c][j] * A0[m][j] * v[j]
// B operand = A0 * (v/vmax) in half (range-safe: A0<=28.2, vs<=1).
// acc is scaled by 1/vmax; vmax is folded back via ush = vmax * u4.
__global__ __launch_bounds__(256) void k_gemm2(float* __restrict__ out) {
    __shared__ __half2 Ahs[16][136];  // [jpair][c]  (A operand: sx)
    __shared__ __half2 Bhs[16][136];  // [jpair][p]  (B operand: A0*vs)
    __shared__ float vsh[K_A];
    __shared__ float dred[128];
    __shared__ float ush[128];

    int n  = blockIdx.z;
    int c0 = blockIdx.y * 128;
    int p0 = blockIdx.x * 128;
    int tid = threadIdx.x;
    int lane = tid & 31, warp = tid >> 5;
    int warpM = warp >> 2, warpN = warp & 3;
    int gid = lane >> 2, tig = lane & 3;

    vsh[tid] = g_vs[tid]; vsh[tid + 256] = g_vs[tid + 256];
    if (tid < 128) dred[tid] = 0.0f;

    const float* sxb = g_sx + (size_t)n * C_DIM * K_A;

    float acc[4][4][4];
#pragma unroll
    for (int a = 0; a < 4; a++)
#pragma unroll
        for (int b = 0; b < 4; b++)
#pragma unroll
            for (int c = 0; c < 4; c++) acc[a][b][c] = 0.0f;

    int cL = tid >> 1;        // 0..127: row index for both tiles
    int jq = tid & 1;         // which 16-j half of the 32-j chunk
    float dp = 0.0f;

    __syncthreads();

    for (int kt = 0; kt < K_A / 32; kt++) {
        int j0 = kt * 32;
        // A tile: sx[c0+cL][j0 + jq*16 .. +15] -> half2
        const float* ap = sxb + (size_t)(c0 + cL) * K_A + j0 + jq * 16;
#pragma unroll
        for (int i = 0; i < 4; i++) {
            float4 a4 = *(const float4*)(ap + i * 4);
            Ahs[jq * 8 + i * 2    ][cL] = __floats2half2_rn(a4.x, a4.y);
            Ahs[jq * 8 + i * 2 + 1][cL] = __floats2half2_rn(a4.z, a4.w);
        }
        // B tile: A0h[(n*4096+p0+cL)][j0 + jq*16 .. +15] * vs -> half2, + dp
        const __half* bp = g_Ah + ((size_t)(n << 12) + p0 + cL) * K_A + j0 + jq * 16;
        uint4 b0 = *(const uint4*)(bp);
        uint4 b1 = *(const uint4*)(bp + 8);
        unsigned us[8] = {b0.x, b0.y, b0.z, b0.w, b1.x, b1.y, b1.z, b1.w};
        const float* vp = vsh + j0 + jq * 16;
#pragma unroll
        for (int w = 0; w < 8; w++) {
            float2 fw = __half22float2(*(__half2*)&us[w]);
            float m0 = fw.x * vp[2 * w];
            float m1 = fw.y * vp[2 * w + 1];
            dp += m0 + m1;
            Bhs[jq * 8 + w][cL] = __floats2half2_rn(m0, m1);
        }
        __syncthreads();
#pragma unroll
        for (int ks = 0; ks < 2; ks++) {
            int kb = ks * 8;
            unsigned a[4][4], b[4][2];
#pragma unroll
            for (int mt = 0; mt < 4; mt++) {
                int cr = warpM * 64 + mt * 16 + gid;
                a[mt][0] = *(unsigned*)&Ahs[kb + tig    ][cr];
                a[mt][1] = *(unsigned*)&Ahs[kb + tig    ][cr + 8];
                a[mt][2] = *(unsigned*)&Ahs[kb + tig + 4][cr];
                a[mt][3] = *(unsigned*)&Ahs[kb + tig + 4][cr + 8];
            }
#pragma unroll
            for (int nt = 0; nt < 4; nt++) {
                int pc = warpN * 32 + nt * 8 + gid;
                b[nt][0] = *(unsigned*)&Bhs[kb + tig    ][pc];
                b[nt][1] = *(unsigned*)&Bhs[kb + tig + 4][pc];
            }
#pragma unroll
            for (int mt = 0; mt < 4; mt++)
#pragma unroll
                for (int nt = 0; nt < 4; nt++) MMA_F16(acc[mt][nt], a[mt], b[nt]);
        }
        __syncthreads();
    }

    // finalize d -> u4 (4th Sinkhorn row pass, fused).
    // dred = sum_j A0*vs = d/vmax -> un-scale for u4; FOLD vmax INTO ush so the
    // vs-scaled accumulator is rescaled to truth:  out = acc * (vmax*u4).
    atomicAdd(&dred[cL], dp);
    __syncthreads();
    if (tid < 128) {
        float vmaxv = g_vmax;
        float d  = dred[tid] * vmaxv;
        float u3 = g_u[(n << 12) + p0 + tid];
        ush[tid] = vmaxv * (u3 / fmaxf(u3 * d, EPS));
    }
    __syncthreads();

#pragma unroll
    for (int mt = 0; mt < 4; mt++) {
        int c = c0 + warpM * 64 + mt * 16 + gid;
#pragma unroll
        for (int nt = 0; nt < 4; nt++) {
            int pl = warpN * 32 + nt * 8 + tig * 2;
            float u0 = ush[pl], u1 = ush[pl + 1];
            size_t o = ((size_t)(n * C_DIM + c)) * HW + p0 + pl;
            *(float2*)(out + o) = make_float2(acc[mt][nt][0] * u0, acc[mt][nt][1] * u1);
            *(float2*)(out + o + (size_t)8 * HW) =
                make_float2(acc[mt][nt][2] * u0, acc[mt][nt][3] * u1);
        }
    }
}

// ---------------- launcher ---------------------------------------------------
extern "C" void kernel_launch(void* const* d_in, const int* in_sizes, int n_in,
                              void* d_out, int out_size) {
    const float* x  = (const float*)d_in[0];
    const int* idx  = (const int*)d_in[1];
    float* out      = (float*)d_out;

    k_init<<<1, 512>>>();
    k_norm<<<M_ROWS / 256, 256>>>(x);
    k_gather<<<(N_B * C_DIM * K_A) / 256, 256>>>(x, idx);
    k_gemm1<<<dim3(32, 4, 16), 256>>>(x);
    k_v1<<<1, 512>>>();
    k_fpass<<<296, 256>>>(1, 1);      // iter1 row + iter2 colsums
    k_vupd<<<1, 512>>>(0);
    k_fpass<<<296, 256>>>(0, 1);      // iter2 row + iter3 colsums
    k_vupd<<<1, 512>>>(0);
    k_fpass<<<296, 256>>>(0, 1);      // iter3 row + iter4 colsums
    k_vupd<<<1, 512>>>(1);            // iter4 col + scaled v for fp16 gemm2
    k_gemm2<<<dim3(32, 2, 16), 256>>>(out);  // iter4 row fused + reconstruction
}

// round 17
// speedup vs baseline: 2.5171x; 1.0887x over previous
#include <cuda_runtime.h>
#include <cuda_fp16.h>
#include <math.h>

// Problem constants
#define N_B   16
#define C_DIM 256
#define HW    4096
#define K_A   512
#define M_ROWS (N_B * HW)          // 65536
#define EPS   1e-12f
#define INV_T 3.33333333333333f    // 1/0.3

// ---------------- scratch (__device__ globals; no runtime allocs) ----------
__device__ __align__(16) __half g_Ah[(size_t)M_ROWS * K_A]; // 64 MB: A0 = exp(scores/T)
__device__ float g_sx[N_B * C_DIM * K_A];       // 8 MB: normalized anchors [n][c][j]
__device__ float g_invn[M_ROWS];                // 1/||x||_c per (n,p)
__device__ float g_u[M_ROWS];
__device__ float g_colsum[K_A];
__device__ float g_t[K_A];
__device__ float g_v[K_A];
__device__ float g_vs[K_A];                     // v / vmax (for fp16 gemm2)
__device__ float g_vmax;
__device__ float g_S0;

#define MMA_F16(d, a, b) asm volatile( \
    "mma.sync.aligned.m16n8k16.row.col.f32.f16.f16.f32 " \
    "{%0,%1,%2,%3},{%4,%5,%6,%7},{%8,%9},{%0,%1,%2,%3};" \
    : "+f"(d[0]), "+f"(d[1]), "+f"(d[2]), "+f"(d[3]) \
    : "r"(a[0]), "r"(a[1]), "r"(a[2]), "r"(a[3]), "r"(b[0]), "r"(b[1]))

// ---------------- init -------------------------------------------------------
__global__ void k_init() {
    int t = threadIdx.x;
    if (t < K_A) { g_colsum[t] = 0.0f; g_t[t] = 0.0f; }
}

// ---------------- per-pixel inverse L2 norm over channels -------------------
__global__ void k_norm(const float* __restrict__ x) {
    int p = blockIdx.x * blockDim.x + threadIdx.x;   // 0..65535
    int n  = p >> 12;
    int pp = p & (HW - 1);
    const float* base = x + (size_t)n * C_DIM * HW + pp;
    float acc = 0.0f;
#pragma unroll 8
    for (int c = 0; c < C_DIM; c++) {
        float v = base[(size_t)c * HW];
        acc += v * v;
    }
    g_invn[p] = 1.0f / fmaxf(sqrtf(acc), EPS);
}

// ---------------- gather normalized anchors: sx[n][c][j] --------------------
__global__ void k_gather(const float* __restrict__ x, const int* __restrict__ idx) {
    int g = blockIdx.x * blockDim.x + threadIdx.x;   // 0 .. 16*256*512-1
    int j = g & (K_A - 1);
    int c = (g >> 9) & (C_DIM - 1);
    int n = g >> 17;
    int p = idx[j];
    float val = x[((size_t)(n * C_DIM + c)) * HW + p] * g_invn[(n << 12) + p];
    g_sx[g] = val;
}

// ---------------- GEMM1 (FP16 MMA): scores -> exp -> A0(half) + column sums --
// S[p,j] = sum_c (x[c][p]*invn[p]) * sx[c][j]; inputs unit-normalized -> fp16
// exact-range. Tiles [kpair][row] half2, layout identical to gemm2 (HW-validated).
// grid (32 p, 4 j, 16 n), block 256 = 8 warps (2Mx4N); warp tile 64x32; k16/chunk
__global__ __launch_bounds__(256) void k_gemm1(const float* __restrict__ x) {
    __shared__ __half2 Xh[8][136];   // [kpair][p]  A operand (x*invn)
    __shared__ __half2 Sh[8][136];   // [kpair][j]  B operand (sx)
    __shared__ float redsh[128];

    int n  = blockIdx.z;
    int j0 = blockIdx.y * 128;
    int p0 = blockIdx.x * 128;
    int tid = threadIdx.x;
    int lane = tid & 31, warp = tid >> 5;
    int warpM = warp >> 2, warpN = warp & 3;
    int gid = lane >> 2, tig = lane & 3;

    if (tid < 128) redsh[tid] = 0.0f;

    const float* xb  = x + (size_t)n * C_DIM * HW;
    const float* sxb = g_sx + (size_t)n * C_DIM * K_A;

    int kp = tid >> 5;   // 0..7: which c-pair of the 16-c chunk
    int pg = tid & 31;   // 0..31: 4-wide column group
    float inv[4];
#pragma unroll
    for (int i = 0; i < 4; i++) inv[i] = g_invn[(n << 12) + p0 + pg * 4 + i];

    float acc[4][4][4];
#pragma unroll
    for (int a = 0; a < 4; a++)
#pragma unroll
        for (int b = 0; b < 4; b++)
#pragma unroll
            for (int c = 0; c < 4; c++) acc[a][b][c] = 0.0f;

    for (int kt = 0; kt < C_DIM / 16; kt++) {
        int c0 = kt * 16 + 2 * kp;
        // X tile: rows c0, c0+1 along p -> half2 (low=even c, high=odd c)
        float4 xa = *(const float4*)(xb + (size_t)c0 * HW + p0 + pg * 4);
        float4 xc = *(const float4*)(xb + (size_t)(c0 + 1) * HW + p0 + pg * 4);
        __half2 h0 = __floats2half2_rn(xa.x * inv[0], xc.x * inv[0]);
        __half2 h1 = __floats2half2_rn(xa.y * inv[1], xc.y * inv[1]);
        __half2 h2v = __floats2half2_rn(xa.z * inv[2], xc.z * inv[2]);
        __half2 h3 = __floats2half2_rn(xa.w * inv[3], xc.w * inv[3]);
        uint4 px;
        px.x = *reinterpret_cast<unsigned*>(&h0);
        px.y = *reinterpret_cast<unsigned*>(&h1);
        px.z = *reinterpret_cast<unsigned*>(&h2v);
        px.w = *reinterpret_cast<unsigned*>(&h3);
        *reinterpret_cast<uint4*>(&Xh[kp][pg * 4]) = px;
        // S tile: rows c0, c0+1 along j -> half2
        float4 sa = *(const float4*)(sxb + (size_t)c0 * K_A + j0 + pg * 4);
        float4 sc = *(const float4*)(sxb + (size_t)(c0 + 1) * K_A + j0 + pg * 4);
        __half2 g0 = __floats2half2_rn(sa.x, sc.x);
        __half2 g1 = __floats2half2_rn(sa.y, sc.y);
        __half2 g2 = __floats2half2_rn(sa.z, sc.z);
        __half2 g3 = __floats2half2_rn(sa.w, sc.w);
        uint4 ps;
        ps.x = *reinterpret_cast<unsigned*>(&g0);
        ps.y = *reinterpret_cast<unsigned*>(&g1);
        ps.z = *reinterpret_cast<unsigned*>(&g2);
        ps.w = *reinterpret_cast<unsigned*>(&g3);
        *reinterpret_cast<uint4*>(&Sh[kp][pg * 4]) = ps;
        __syncthreads();
        // one k16 MMA step over the 16-c chunk
        unsigned a[4][4], b[4][2];
#pragma unroll
        for (int mt = 0; mt < 4; mt++) {
            int pr = warpM * 64 + mt * 16 + gid;
            a[mt][0] = *(unsigned*)&Xh[tig    ][pr];
            a[mt][1] = *(unsigned*)&Xh[tig    ][pr + 8];
            a[mt][2] = *(unsigned*)&Xh[tig + 4][pr];
            a[mt][3] = *(unsigned*)&Xh[tig + 4][pr + 8];
        }
#pragma unroll
        for (int nt = 0; nt < 4; nt++) {
            int jc = warpN * 32 + nt * 8 + gid;
            b[nt][0] = *(unsigned*)&Sh[tig    ][jc];
            b[nt][1] = *(unsigned*)&Sh[tig + 4][jc];
        }
#pragma unroll
        for (int mt = 0; mt < 4; mt++)
#pragma unroll
            for (int nt = 0; nt < 4; nt++) MMA_F16(acc[mt][nt], a[mt], b[nt]);
        __syncthreads();
    }

    // epilogue: exp, round to half, store, accumulate column sums of ROUNDED vals
    float s[4][2];
#pragma unroll
    for (int nt = 0; nt < 4; nt++) { s[nt][0] = 0.0f; s[nt][1] = 0.0f; }
#pragma unroll
    for (int mt = 0; mt < 4; mt++) {
        int p = p0 + warpM * 64 + mt * 16 + gid;
        size_t base = ((size_t)(n << 12) + p) * K_A + j0 + warpN * 32;
#pragma unroll
        for (int nt = 0; nt < 4; nt++) {
            __half2 h01 = __floats2half2_rn(__expf(acc[mt][nt][0] * INV_T),
                                            __expf(acc[mt][nt][1] * INV_T));
            __half2 h23 = __floats2half2_rn(__expf(acc[mt][nt][2] * INV_T),
                                            __expf(acc[mt][nt][3] * INV_T));
            *(__half2*)(g_Ah + base + nt * 8 + tig * 2)                 = h01;
            *(__half2*)(g_Ah + base + (size_t)8 * K_A + nt * 8 + tig * 2) = h23;
            float2 r01 = __half22float2(h01);
            float2 r23 = __half22float2(h23);
            s[nt][0] += r01.x + r23.x;
            s[nt][1] += r01.y + r23.y;
        }
    }
#pragma unroll
    for (int nt = 0; nt < 4; nt++) {
        float v0 = s[nt][0], v1 = s[nt][1];
#pragma unroll
        for (int off = 4; off < 32; off <<= 1) {
            v0 += __shfl_xor_sync(0xFFFFFFFFu, v0, off);
            v1 += __shfl_xor_sync(0xFFFFFFFFu, v1, off);
        }
        if (lane < 4) {
            atomicAdd(&redsh[warpN * 32 + nt * 8 + lane * 2],     v0);
            atomicAdd(&redsh[warpN * 32 + nt * 8 + lane * 2 + 1], v1);
        }
    }
    __syncthreads();
    if (tid < 128) atomicAdd(&g_colsum[j0 + tid], redsh[tid]);
}

// ---------------- v1 from column sums + total mass --------------------------
__global__ void k_v1() {
    __shared__ float sr[K_A];
    int tid = threadIdx.x;
    float c = g_colsum[tid];
    sr[tid] = c;
    __syncthreads();
    for (int s = K_A / 2; s > 0; s >>= 1) {
        if (tid < s) sr[tid] += sr[tid + s];
        __syncthreads();
    }
    float S0 = sr[0];
    if (tid == 0) g_S0 = S0;
    g_v[tid] = 1.0f / fmaxf(c / S0, EPS);
    g_t[tid] = 0.0f;
}

// ---------------- fused row pass + next col pass (half A) --------------------
__global__ void k_fpass(int first, int compute_t) {
    __shared__ float vs[K_A];
    __shared__ float ts[K_A];
    int tid = threadIdx.x;
    vs[tid] = g_v[tid]; vs[tid + 256] = g_v[tid + 256];
    ts[tid] = 0.0f;     ts[tid + 256] = 0.0f;
    __syncthreads();

    int warp = tid >> 5, lane = tid & 31;
    int stride = gridDim.x * 8;
    int gw = blockIdx.x * 8 + warp;
    float S0inv = 1.0f / g_S0;

    float tp[16];
#pragma unroll
    for (int i = 0; i < 16; i++) tp[i] = 0.0f;

    for (int m = gw; m < M_ROWS; m += stride) {
        const __half* row = g_Ah + (size_t)m * K_A + lane * 16;
        uint4 q0 = *(const uint4*)(row);
        uint4 q1 = *(const uint4*)(row + 8);
        unsigned us[8] = {q0.x, q0.y, q0.z, q0.w, q1.x, q1.y, q1.z, q1.w};
        float f[16];
#pragma unroll
        for (int w = 0; w < 8; w++) {
            float2 fw = __half22float2(*(__half2*)&us[w]);
            f[2 * w] = fw.x; f[2 * w + 1] = fw.y;
        }
        const float* vv = vs + lane * 16;
        float d = 0.0f;
#pragma unroll
        for (int i = 0; i < 16; i++) d += f[i] * vv[i];
#pragma unroll
        for (int off = 16; off > 0; off >>= 1) d += __shfl_xor_sync(0xFFFFFFFFu, d, off);
        float u_old = first ? S0inv : g_u[m];
        float u_new = u_old / fmaxf(u_old * d, EPS);
        if (lane == 0) g_u[m] = u_new;
        if (compute_t) {
#pragma unroll
            for (int i = 0; i < 16; i++) tp[i] += f[i] * u_new;
        }
    }
    if (compute_t) {
#pragma unroll
        for (int i = 0; i < 16; i++) atomicAdd(&ts[lane * 16 + i], tp[i]);
        __syncthreads();
        atomicAdd(&g_t[tid], ts[tid]);
        atomicAdd(&g_t[tid + 256], ts[tid + 256]);
    }
}

// ---------------- v update; last call also produces scaled v -----------------
__global__ void k_vupd(int make_scaled) {
    __shared__ float sm[K_A];
    int tid = threadIdx.x;   // 512 threads
    float v = g_v[tid], t = g_t[tid];
    float vn = v / fmaxf(v * t, EPS);
    g_v[tid] = vn;
    g_t[tid] = 0.0f;
    if (make_scaled) {
        sm[tid] = vn;
        __syncthreads();
        for (int s = K_A / 2; s > 0; s >>= 1) {
            if (tid < s) sm[tid] = fmaxf(sm[tid], sm[tid + s]);
            __syncthreads();
        }
        float vmax = sm[0];
        if (tid == 0) g_vmax = vmax;
        g_vs[tid] = vn / vmax;
    }
}

// ---------------- GEMM2 (FP16 MMA) + fused 4th row pass ----------------------
// out[n,c,p] = u4_p * sum_j sx[c][j] * A0[m][j] * v[j]
// B operand = A0 * (v/vmax) in half (range-safe: A0<=28.2, vs<=1).
// acc is scaled by 1/vmax; vmax is folded back via ush = vmax * u4.
__global__ __launch_bounds__(256) void k_gemm2(float* __restrict__ out) {
    __shared__ __half2 Ahs[16][136];  // [jpair][c]  (A operand: sx)
    __shared__ __half2 Bhs[16][136];  // [jpair][p]  (B operand: A0*vs)
    __shared__ float vsh[K_A];
    __shared__ float dred[128];
    __shared__ float ush[128];

    int n  = blockIdx.z;
    int c0 = blockIdx.y * 128;
    int p0 = blockIdx.x * 128;
    int tid = threadIdx.x;
    int lane = tid & 31, warp = tid >> 5;
    int warpM = warp >> 2, warpN = warp & 3;
    int gid = lane >> 2, tig = lane & 3;

    vsh[tid] = g_vs[tid]; vsh[tid + 256] = g_vs[tid + 256];
    if (tid < 128) dred[tid] = 0.0f;

    const float* sxb = g_sx + (size_t)n * C_DIM * K_A;

    float acc[4][4][4];
#pragma unroll
    for (int a = 0; a < 4; a++)
#pragma unroll
        for (int b = 0; b < 4; b++)
#pragma unroll
            for (int c = 0; c < 4; c++) acc[a][b][c] = 0.0f;

    int cL = tid >> 1;        // 0..127: row index for both tiles
    int jq = tid & 1;         // which 16-j half of the 32-j chunk
    float dp = 0.0f;

    __syncthreads();

    for (int kt = 0; kt < K_A / 32; kt++) {
        int j0 = kt * 32;
        // A tile: sx[c0+cL][j0 + jq*16 .. +15] -> half2
        const float* ap = sxb + (size_t)(c0 + cL) * K_A + j0 + jq * 16;
#pragma unroll
        for (int i = 0; i < 4; i++) {
            float4 a4 = *(const float4*)(ap + i * 4);
            Ahs[jq * 8 + i * 2    ][cL] = __floats2half2_rn(a4.x, a4.y);
            Ahs[jq * 8 + i * 2 + 1][cL] = __floats2half2_rn(a4.z, a4.w);
        }
        // B tile: A0h[(n*4096+p0+cL)][j0 + jq*16 .. +15] * vs -> half2, + dp
        const __half* bp = g_Ah + ((size_t)(n << 12) + p0 + cL) * K_A + j0 + jq * 16;
        uint4 b0 = *(const uint4*)(bp);
        uint4 b1 = *(const uint4*)(bp + 8);
        unsigned us[8] = {b0.x, b0.y, b0.z, b0.w, b1.x, b1.y, b1.z, b1.w};
        const float* vp = vsh + j0 + jq * 16;
#pragma unroll
        for (int w = 0; w < 8; w++) {
            float2 fw = __half22float2(*(__half2*)&us[w]);
            float m0 = fw.x * vp[2 * w];
            float m1 = fw.y * vp[2 * w + 1];
            dp += m0 + m1;
            Bhs[jq * 8 + w][cL] = __floats2half2_rn(m0, m1);
        }
        __syncthreads();
#pragma unroll
        for (int ks = 0; ks < 2; ks++) {
            int kb = ks * 8;
            unsigned a[4][4], b[4][2];
#pragma unroll
            for (int mt = 0; mt < 4; mt++) {
                int cr = warpM * 64 + mt * 16 + gid;
                a[mt][0] = *(unsigned*)&Ahs[kb + tig    ][cr];
                a[mt][1] = *(unsigned*)&Ahs[kb + tig    ][cr + 8];
                a[mt][2] = *(unsigned*)&Ahs[kb + tig + 4][cr];
                a[mt][3] = *(unsigned*)&Ahs[kb + tig + 4][cr + 8];
            }
#pragma unroll
            for (int nt = 0; nt < 4; nt++) {
                int pc = warpN * 32 + nt * 8 + gid;
                b[nt][0] = *(unsigned*)&Bhs[kb + tig    ][pc];
                b[nt][1] = *(unsigned*)&Bhs[kb + tig + 4][pc];
            }
#pragma unroll
            for (int mt = 0; mt < 4; mt++)
#pragma unroll
                for (int nt = 0; nt < 4; nt++) MMA_F16(acc[mt][nt], a[mt], b[nt]);
        }
        __syncthreads();
    }

    // finalize d -> u4 (4th Sinkhorn row pass, fused).
    // dred = sum_j A0*vs = d/vmax -> un-scale for u4; FOLD vmax INTO ush so the
    // vs-scaled accumulator is rescaled to truth:  out = acc * (vmax*u4).
    atomicAdd(&dred[cL], dp);
    __syncthreads();
    if (tid < 128) {
        float vmaxv = g_vmax;
        float d  = dred[tid] * vmaxv;
        float u3 = g_u[(n << 12) + p0 + tid];
        ush[tid] = vmaxv * (u3 / fmaxf(u3 * d, EPS));
    }
    __syncthreads();

#pragma unroll
    for (int mt = 0; mt < 4; mt++) {
        int c = c0 + warpM * 64 + mt * 16 + gid;
#pragma unroll
        for (int nt = 0; nt < 4; nt++) {
            int pl = warpN * 32 + nt * 8 + tig * 2;
            float u0 = ush[pl], u1 = ush[pl + 1];
            size_t o = ((size_t)(n * C_DIM + c)) * HW + p0 + pl;
            *(float2*)(out + o) = make_float2(acc[mt][nt][0] * u0, acc[mt][nt][1] * u1);
            *(float2*)(out + o + (size_t)8 * HW) =
                make_float2(acc[mt][nt][2] * u0, acc[mt][nt][3] * u1);
        }
    }
}

// ---------------- launcher ---------------------------------------------------
extern "C" void kernel_launch(void* const* d_in, const int* in_sizes, int n_in,
                              void* d_out, int out_size) {
    const float* x  = (const float*)d_in[0];
    const int* idx  = (const int*)d_in[1];
    float* out      = (float*)d_out;

    k_init<<<1, 512>>>();
    k_norm<<<M_ROWS / 256, 256>>>(x);
    k_gather<<<(N_B * C_DIM * K_A) / 256, 256>>>(x, idx);
    k_gemm1<<<dim3(32, 4, 16), 256>>>(x);
    k_v1<<<1, 512>>>();
    k_fpass<<<296, 256>>>(1, 1);      // iter1 row + iter2 colsums
    k_vupd<<<1, 512>>>(0);
    k_fpass<<<296, 256>>>(0, 1);      // iter2 row + iter3 colsums
    k_vupd<<<1, 512>>>(0);
    k_fpass<<<296, 256>>>(0, 1);      // iter3 row + iter4 colsums
    k_vupd<<<1, 512>>>(1);            // iter4 col + scaled v for fp16 gemm2
    k_gemm2<<<dim3(32, 2, 16), 256>>>(out);  // iter4 row fused + reconstruction
}